// round 16
// baseline (speedup 1.0000x reference)
#include <cuda_runtime.h>
#include <cstdint>
#include <cstddef>

// CTRNN round 16: rec kernel unchanged (converged ~592 us).
// Pre-pass v6: NO shared memory, NO barriers.
//   R12-R15 pre-passes all pinned at 135-149 us vs a ~58 us dual-pipe floor;
//   the invariant was smem x staging with per-block barriers fencing load
//   batching. v6: Win[j,:] in 64 registers (R13 layout); x read directly via
//   warp-uniform __ldg (1 sector/instr, L1-resident after first touch,
//   4 KB/block working set). No syncthreads anywhere in the loop -> ptxas
//   free to software-pipeline 256 LDG + 512 FMA2 per block with real MLP.
//   ~80 regs -> launch_bounds(256,3), grid 444 (3 CTAs/SM, 6 warps/SMSP).

#define T_STEPS 512
#define BATCH   256
#define IN_SZ   64
#define HID     256
#define NTHR    512
#define NCTA    (BATCH / 2)

#define NGROUP        4
#define ROWS_PER_G    64
#define CHUNKS_PER_G  8           // 32 smem W rows per group
#define SMEM_ROWS_G   32
#define RF_U64        16          // 32 reg W rows per group (per j)
#define NSLOTS        (CHUNKS_PER_G + RF_U64 / 2)   // 16
#define TOTAL_CHUNKS  (NGROUP * CHUNKS_PER_G)       // 32

typedef unsigned long long u64;

#define SMEM_W_BYTES   (TOTAL_CHUNKS * HID * 16)     // 131072
#define HAUG_STRIDE    72                            // 64 rows + pad (16B mult)
#define HAUG_OFF       SMEM_W_BYTES
#define RED_OFF        (HAUG_OFF + NGROUP * 2 * HAUG_STRIDE * 4)   // +2304
#define RED_PAR_FLOATS (2 * NGROUP * HID)            // 2048 per parity
#define SMEM_TOTAL     (RED_OFF + 2 * RED_PAR_FLOATS * 4)          // 149760

// 134 MB scratch for pre[t][b][j] (device-global array: sanctioned scratch).
__device__ float g_pre[(size_t)T_STEPS * BATCH * HID];

__device__ __forceinline__ u64 fma2(u64 a, u64 b, u64 c) {
    u64 d;
    asm("fma.rn.f32x2 %0, %1, %2, %3;" : "=l"(d) : "l"(a), "l"(b), "l"(c));
    return d;
}
__device__ __forceinline__ u64 add2(u64 a, u64 b) {
    u64 d;
    asm("add.rn.f32x2 %0, %1, %2;" : "=l"(d) : "l"(a), "l"(b));
    return d;
}
__device__ __forceinline__ float sum2(u64 a) {
    float lo, hi;
    asm("mov.b64 {%0, %1}, %2;" : "=f"(lo), "=f"(hi) : "l"(a));
    return lo + hi;
}

// ---------------------------------------------------------------------------
// Kernel 1: pre-pass v6 (smem-free).
// 444 CTAs x 256 threads (3 CTAs/SM), persistent over 8192 16-row blocks.
// Thread = output unit j; Win[j,:] in 32 u64 regs; x via uniform __ldg.
// Paired-row inner loop: 4 independent chains, 2 independent LDG streams.
// ---------------------------------------------------------------------------
#define PP_NCTA 444
#define PP_THR  256
#define PP_BLK_ROWS 16
#define PP_NBLK (T_STEPS * BATCH / PP_BLK_ROWS)     // 8192

__global__ void __launch_bounds__(PP_THR, 3)
ctrnn_prepass(const float* __restrict__ x,
              const float* __restrict__ noise,
              const float* __restrict__ Win,
              const float* __restrict__ bin,
              const float* __restrict__ bhh)
{
    const int j = threadIdx.x;
    u64 w[IN_SZ / 2];
    #pragma unroll
    for (int m = 0; m < IN_SZ / 2; ++m)
        w[m] = *reinterpret_cast<const u64*>(&Win[j * IN_SZ + 2 * m]);
    const float bias = bin[j] + bhh[j];

    for (int blk = blockIdx.x; blk < PP_NBLK; blk += PP_NCTA) {
        const int   t  = blk >> 4;              // 16 blocks per timestep
        const float nb = __ldg(&noise[(size_t)t * HID + j]) + bias;
        const size_t row0 = (size_t)blk * PP_BLK_ROWS;
        const float* xp = x + row0 * IN_SZ;

        // ---- paired rows: 8 pairs, 4 chains, 2 LDG streams, no fences ----
        #pragma unroll 2
        for (int rp = 0; rp < PP_BLK_ROWS / 2; ++rp) {
            const ulonglong2* xrA =
                reinterpret_cast<const ulonglong2*>(xp + (2 * rp) * IN_SZ);
            const ulonglong2* xrB =
                reinterpret_cast<const ulonglong2*>(xp + (2 * rp + 1) * IN_SZ);
            u64 aA0 = 0, aA1 = 0, aB0 = 0, aB1 = 0;
            #pragma unroll
            for (int m = 0; m < IN_SZ / 4; ++m) {
                const ulonglong2 xvA = __ldg(&xrA[m]);   // warp-uniform, L1-hot
                const ulonglong2 xvB = __ldg(&xrB[m]);
                aA0 = fma2(w[2 * m],     xvA.x, aA0);
                aA1 = fma2(w[2 * m + 1], xvA.y, aA1);
                aB0 = fma2(w[2 * m],     xvB.x, aB0);
                aB1 = fma2(w[2 * m + 1], xvB.y, aB1);
            }
            g_pre[(row0 + 2 * rp)     * HID + j] = sum2(add2(aA0, aA1)) + nb;
            g_pre[(row0 + 2 * rp + 1) * HID + j] = sum2(add2(aB0, aB1)) + nb;
        }
    }
}

// ---------------------------------------------------------------------------
// Kernel 2: recurrent loop (aug K = 256, Whh only) — unchanged from R13.
// ---------------------------------------------------------------------------
__global__ void __launch_bounds__(NTHR, 1)
ctrnn_rec_kernel(const float* __restrict__ h0,
                 const float* __restrict__ Whh,
                 float* __restrict__ out,
                 float* __restrict__ hlast)
{
    extern __shared__ unsigned char smem_raw[];
    ulonglong2* Wsm = reinterpret_cast<ulonglong2*>(smem_raw);
    float* haug = reinterpret_cast<float*>(smem_raw + HAUG_OFF);  // [4][2][72]
    float* red  = reinterpret_cast<float*>(smem_raw + RED_OFF);   // [2][2][4][256]

    const int tid = threadIdx.x;
    const int g   = tid >> 7;          // k-group 0..3
    const int jl  = tid & 127;
    const int j0  = jl;
    const int j1  = jl + 128;
    const int b0  = blockIdx.x * 2;
    const int b1  = b0 + 1;

    // ---- stage W smem: chunk i covers Whh cols 64g+4i..+3, rows j0/j1 ----
    for (int i = 0; i < CHUNKS_PER_G; ++i) {
        const int col = ROWS_PER_G * g + 4 * i;
        *reinterpret_cast<float4*>(&Wsm[(g * CHUNKS_PER_G + i) * HID + j0]) =
            *reinterpret_cast<const float4*>(&Whh[j0 * HID + col]);
        *reinterpret_cast<float4*>(&Wsm[(g * CHUNKS_PER_G + i) * HID + j1]) =
            *reinterpret_cast<const float4*>(&Whh[j1 * HID + col]);
    }

    // ---- register W rows: Whh cols 64g+32 .. 64g+63 (16 u64 per j) ----
    u64 wr0[RF_U64], wr1[RF_U64];
    #pragma unroll
    for (int m = 0; m < RF_U64; ++m) {
        const int col = ROWS_PER_G * g + SMEM_ROWS_G + 2 * m;
        wr0[m] = *reinterpret_cast<const u64*>(&Whh[j0 * HID + col]);
        wr1[m] = *reinterpret_cast<const u64*>(&Whh[j1 * HID + col]);
    }

    // ---- finalize identity: one (batch, j) item per thread ----
    const int  fb   = jl >> 6;                 // 0 = batch A, 1 = batch B
    const int  fr   = jl & 63;                 // local row in slice
    const int  fj   = ROWS_PER_G * g + fr;     // global j
    const int  fbat = fb ? b1 : b0;

    float* myA = haug + (g * 2 + 0) * HAUG_STRIDE;
    float* myB = haug + (g * 2 + 1) * HAUG_STRIDE;
    float* fbuf = fb ? myB : myA;              // slice this thread finalizes into

    // ---- initial h staging (each thread stages its finalize item) ----
    fbuf[fr] = h0[fbat * HID + fj];
    __syncthreads();

    const ulonglong2* wp0 = Wsm + (size_t)(g * CHUNKS_PER_G) * HID + j0;
    const ulonglong2* wp1 = Wsm + (size_t)(g * CHUNKS_PER_G) * HID + j1;

    // ---- prime depth-1 W lookahead (chunk 0) ----
    ulonglong2 wb0 = wp0[0];
    ulonglong2 wb1 = wp1[0];

    for (int t = 0; t < T_STEPS; ++t) {
        float* redp = red + (t & 1) * RED_PAR_FLOATS;

        // prefetch this step's static pre-activation for my finalize item
        const float pre_v = g_pre[((size_t)t * BATCH + fbat) * HID + fj];

        // ---- interleaved FMA phase: (c r) x 8 slots ----
        u64 aA0 = 0, aA1 = 0, aB0 = 0, aB1 = 0;
        int ci = 0, ri = 0;

        #pragma unroll
        for (int k = 0; k < NSLOTS; ++k) {
            if (k & 1) {
                // RF slot ri: local rows 32+4*ri
                ulonglong2 ha = *reinterpret_cast<const ulonglong2*>(&myA[SMEM_ROWS_G + 4 * ri]);
                ulonglong2 hb = *reinterpret_cast<const ulonglong2*>(&myB[SMEM_ROWS_G + 4 * ri]);
                aA0 = fma2(wr0[2 * ri], ha.x, aA0);  aA0 = fma2(wr0[2 * ri + 1], ha.y, aA0);
                aA1 = fma2(wr1[2 * ri], ha.x, aA1);  aA1 = fma2(wr1[2 * ri + 1], ha.y, aA1);
                aB0 = fma2(wr0[2 * ri], hb.x, aB0);  aB0 = fma2(wr0[2 * ri + 1], hb.y, aB0);
                aB1 = fma2(wr1[2 * ri], hb.x, aB1);  aB1 = fma2(wr1[2 * ri + 1], hb.y, aB1);
                ++ri;
            } else {
                // chunk slot ci: consume buffered W, issue chunk (ci+1)%8;
                // last chunk slot fetches NEXT step's chunk 0 pre-barrier.
                const ulonglong2 w0 = wb0;
                const ulonglong2 w1 = wb1;
                int nc = ci + 1;
                if (nc >= CHUNKS_PER_G) nc = 0;
                wb0 = wp0[(size_t)nc * HID];
                wb1 = wp1[(size_t)nc * HID];

                ulonglong2 ha = *reinterpret_cast<const ulonglong2*>(&myA[4 * ci]);
                ulonglong2 hb = *reinterpret_cast<const ulonglong2*>(&myB[4 * ci]);
                aA0 = fma2(w0.x, ha.x, aA0);  aA0 = fma2(w0.y, ha.y, aA0);
                aA1 = fma2(w1.x, ha.x, aA1);  aA1 = fma2(w1.y, ha.y, aA1);
                aB0 = fma2(w0.x, hb.x, aB0);  aB0 = fma2(w0.y, hb.y, aB0);
                aB1 = fma2(w1.x, hb.x, aB1);  aB1 = fma2(w1.y, hb.y, aB1);
                ++ci;
            }
        }

        redp[(0 * NGROUP + g) * HID + j0] = sum2(aA0);
        redp[(0 * NGROUP + g) * HID + j1] = sum2(aA1);
        redp[(1 * NGROUP + g) * HID + j0] = sum2(aB0);
        redp[(1 * NGROUP + g) * HID + j1] = sum2(aB1);
        __syncthreads();                       // the ONE full-CTA barrier

        // ---- finalize my single (batch, j) item ----
        {
            const float* rb = redp + fb * NGROUP * HID;
            const float s = rb[0 * HID + fj] + rb[1 * HID + fj]
                          + rb[2 * HID + fj] + rb[3 * HID + fj];
            const float hn = fmaxf(fbuf[fr] * 0.8f + (s + pre_v) * 0.2f, 0.f);
            if (out) out[((size_t)t * BATCH + fbat) * HID + fj] = hn;
            fbuf[fr] = hn;
        }

        asm volatile("bar.sync %0, %1;" :: "r"(g + 1), "r"(128) : "memory");
    }

    if (hlast)
        hlast[fbat * HID + fj] = fbuf[fr];
}

extern "C" void kernel_launch(void* const* d_in, const int* in_sizes, int n_in,
                              void* d_out, int out_size)
{
    const float* x     = (const float*)d_in[0];   // [512,256,64]
    const float* h0    = (const float*)d_in[1];   // [256,256]
    const float* noise = (const float*)d_in[2];   // [512,256]
    const float* Win   = (const float*)d_in[3];   // [256,64]
    const float* bin   = (const float*)d_in[4];   // [256]
    const float* Whh   = (const float*)d_in[5];   // [256,256]
    const float* bhh   = (const float*)d_in[6];   // [256]

    const size_t TBH = (size_t)T_STEPS * BATCH * HID;
    const size_t BH  = (size_t)BATCH * HID;

    float* out   = nullptr;
    float* hlast = nullptr;
    if ((size_t)out_size >= TBH) {
        out = (float*)d_out;
        if ((size_t)out_size >= TBH + BH) hlast = (float*)d_out + TBH;
    } else {
        hlast = (float*)d_out;
    }

    static bool attr_set = false;
    if (!attr_set) {
        cudaFuncSetAttribute(ctrnn_rec_kernel,
                             cudaFuncAttributeMaxDynamicSharedMemorySize, SMEM_TOTAL);
        attr_set = true;
    }

    ctrnn_prepass<<<PP_NCTA, PP_THR>>>(x, noise, Win, bin, bhh);
    ctrnn_rec_kernel<<<NCTA, NTHR, SMEM_TOTAL>>>(h0, Whh, out, hlast);
}

// round 17
// speedup vs baseline: 1.6228x; 1.6228x over previous
#include <cuda_runtime.h>
#include <cstdint>
#include <cstddef>

// CTRNN round 17: rec kernel byte-identical to R13 (stable ~592 us).
// Pre-pass v7: R13's proven LDS-broadcast body, new occupancy geometry.
//   Ledger: per SM per block-pair the crossbar needs 4096 wf AND the FMA
//   pipes 4096 cyc (floor 63 us overlapped / 126 serialized; R13 measured
//   135 = serialized at 4 warps/SMSP, rate 8/39=0.20 < 0.25 needed).
//   v7: 128-thread CTAs, thread = j within a statically assigned j-half
//   (W stays fixed in 64 regs), launch_bounds(128,5) -> cap 100 vs ~86 used
//   (cp.async staging, no register-held prefetch). 5 CTAs/SM = 5 warps/SMSP
//   -> 10/39 = 0.256 >= 0.25: crosses the serialization threshold.

#define T_STEPS 512
#define BATCH   256
#define IN_SZ   64
#define HID     256
#define NTHR    512
#define NCTA    (BATCH / 2)

#define NGROUP        4
#define ROWS_PER_G    64
#define CHUNKS_PER_G  8           // 32 smem W rows per group
#define SMEM_ROWS_G   32
#define RF_U64        16          // 32 reg W rows per group (per j)
#define NSLOTS        (CHUNKS_PER_G + RF_U64 / 2)   // 16
#define TOTAL_CHUNKS  (NGROUP * CHUNKS_PER_G)       // 32

typedef unsigned long long u64;

#define SMEM_W_BYTES   (TOTAL_CHUNKS * HID * 16)     // 131072
#define HAUG_STRIDE    72                            // 64 rows + pad (16B mult)
#define HAUG_OFF       SMEM_W_BYTES
#define RED_OFF        (HAUG_OFF + NGROUP * 2 * HAUG_STRIDE * 4)   // +2304
#define RED_PAR_FLOATS (2 * NGROUP * HID)            // 2048 per parity
#define SMEM_TOTAL     (RED_OFF + 2 * RED_PAR_FLOATS * 4)          // 149760

// 134 MB scratch for pre[t][b][j] (device-global array: sanctioned scratch).
__device__ float g_pre[(size_t)T_STEPS * BATCH * HID];

__device__ __forceinline__ u64 fma2(u64 a, u64 b, u64 c) {
    u64 d;
    asm("fma.rn.f32x2 %0, %1, %2, %3;" : "=l"(d) : "l"(a), "l"(b), "l"(c));
    return d;
}
__device__ __forceinline__ u64 add2(u64 a, u64 b) {
    u64 d;
    asm("add.rn.f32x2 %0, %1, %2;" : "=l"(d) : "l"(a), "l"(b));
    return d;
}
__device__ __forceinline__ float sum2(u64 a) {
    float lo, hi;
    asm("mov.b64 {%0, %1}, %2;" : "=f"(lo), "=f"(hi) : "l"(a));
    return lo + hi;
}

// ---------------------------------------------------------------------------
// Kernel 1: pre-pass v7.
// 740 CTAs x 128 threads (5 CTAs/SM). CTA = (block-stride lane, j-half):
// jh = blockIdx.x & 1 (static -> W regs fixed), blocks strided by 370.
// Thread j = jh*128 + tid; Win[j,:] in 32 u64 regs. x blocks (16 rows)
// staged via cp.async double buffering (2 x 16B per thread per buffer).
// Paired-row inner loop: 4 chains, 2 broadcast-LDS streams (R13 body).
// ---------------------------------------------------------------------------
#define PP_THR   128
#define PP_CTAS  740
#define PP_PAIRS (PP_CTAS / 2)                      // 370 block-stride lanes
#define PP_BLK_ROWS 16
#define PP_NBLK (T_STEPS * BATCH / PP_BLK_ROWS)     // 8192
#define PP_XBUF_FLOATS (PP_BLK_ROWS * IN_SZ)        // 1024

__global__ void __launch_bounds__(PP_THR, 5)
ctrnn_prepass(const float* __restrict__ x,
              const float* __restrict__ noise,
              const float* __restrict__ Win,
              const float* __restrict__ bin,
              const float* __restrict__ bhh)
{
    __shared__ float xs[2][PP_XBUF_FLOATS];         // 2 x 4 KB

    const int tid = threadIdx.x;
    const int jh  = blockIdx.x & 1;
    const int j   = jh * PP_THR + tid;              // fixed for this CTA

    u64 w[IN_SZ / 2];
    #pragma unroll
    for (int m = 0; m < IN_SZ / 2; ++m)
        w[m] = *reinterpret_cast<const u64*>(&Win[j * IN_SZ + 2 * m]);
    const float bias = bin[j] + bhh[j];

    // cp.async destinations: thread covers float4 slots tid and tid+128
    const uint32_t xs_base = (uint32_t)__cvta_generic_to_shared(&xs[0][0]);
    const uint32_t d0a = xs_base + tid * 16;
    const uint32_t d0b = xs_base + (tid + PP_THR) * 16;
    const uint32_t d1a = d0a + PP_XBUF_FLOATS * 4;
    const uint32_t d1b = d0b + PP_XBUF_FLOATS * 4;

    int blk = blockIdx.x >> 1;
    {
        const float* src = x + (size_t)blk * PP_BLK_ROWS * IN_SZ;
        asm volatile("cp.async.cg.shared.global [%0], [%1], 16;\n\t"
                     "cp.async.cg.shared.global [%2], [%3], 16;\n\t"
                     "cp.async.commit_group;\n\t"
                     "cp.async.wait_group 0;"
                     :: "r"(d0a), "l"(src + 4 * tid),
                        "r"(d0b), "l"(src + 4 * (tid + PP_THR))
                     : "memory");
    }
    __syncthreads();
    int cur = 0;

    while (true) {
        const int nblk = blk + PP_PAIRS;
        const bool has_next = nblk < PP_NBLK;

        if (has_next) {
            const float* src = x + (size_t)nblk * PP_BLK_ROWS * IN_SZ;
            asm volatile("cp.async.cg.shared.global [%0], [%1], 16;\n\t"
                         "cp.async.cg.shared.global [%2], [%3], 16;\n\t"
                         "cp.async.commit_group;"
                         :: "r"(cur ? d0a : d1a), "l"(src + 4 * tid),
                            "r"(cur ? d0b : d1b), "l"(src + 4 * (tid + PP_THR))
                         : "memory");
        }

        const int   t  = blk >> 4;                  // 16 blocks per timestep
        const float nb = noise[(size_t)t * HID + j] + bias;
        const size_t row0 = (size_t)blk * PP_BLK_ROWS;
        const float* xb = xs[cur];

        // ---- paired rows: 8 pairs, 4 chains, 2 broadcast-LDS streams ----
        #pragma unroll 2
        for (int rp = 0; rp < PP_BLK_ROWS / 2; ++rp) {
            const ulonglong2* xrA =
                reinterpret_cast<const ulonglong2*>(&xb[(2 * rp) * IN_SZ]);
            const ulonglong2* xrB =
                reinterpret_cast<const ulonglong2*>(&xb[(2 * rp + 1) * IN_SZ]);
            u64 aA0 = 0, aA1 = 0, aB0 = 0, aB1 = 0;
            #pragma unroll
            for (int m = 0; m < IN_SZ / 4; ++m) {
                ulonglong2 xvA = xrA[m];
                ulonglong2 xvB = xrB[m];
                aA0 = fma2(w[2 * m],     xvA.x, aA0);
                aA1 = fma2(w[2 * m + 1], xvA.y, aA1);
                aB0 = fma2(w[2 * m],     xvB.x, aB0);
                aB1 = fma2(w[2 * m + 1], xvB.y, aB1);
            }
            g_pre[(row0 + 2 * rp)     * HID + j] = sum2(add2(aA0, aA1)) + nb;
            g_pre[(row0 + 2 * rp + 1) * HID + j] = sum2(add2(aB0, aB1)) + nb;
        }

        if (!has_next) break;
        asm volatile("cp.async.wait_group 0;" ::: "memory");
        __syncthreads();
        cur ^= 1;
        blk = nblk;
    }
}

// ---------------------------------------------------------------------------
// Kernel 2: recurrent loop (aug K = 256, Whh only) — unchanged from R13.
// ---------------------------------------------------------------------------
__global__ void __launch_bounds__(NTHR, 1)
ctrnn_rec_kernel(const float* __restrict__ h0,
                 const float* __restrict__ Whh,
                 float* __restrict__ out,
                 float* __restrict__ hlast)
{
    extern __shared__ unsigned char smem_raw[];
    ulonglong2* Wsm = reinterpret_cast<ulonglong2*>(smem_raw);
    float* haug = reinterpret_cast<float*>(smem_raw + HAUG_OFF);  // [4][2][72]
    float* red  = reinterpret_cast<float*>(smem_raw + RED_OFF);   // [2][2][4][256]

    const int tid = threadIdx.x;
    const int g   = tid >> 7;          // k-group 0..3
    const int jl  = tid & 127;
    const int j0  = jl;
    const int j1  = jl + 128;
    const int b0  = blockIdx.x * 2;
    const int b1  = b0 + 1;

    // ---- stage W smem: chunk i covers Whh cols 64g+4i..+3, rows j0/j1 ----
    for (int i = 0; i < CHUNKS_PER_G; ++i) {
        const int col = ROWS_PER_G * g + 4 * i;
        *reinterpret_cast<float4*>(&Wsm[(g * CHUNKS_PER_G + i) * HID + j0]) =
            *reinterpret_cast<const float4*>(&Whh[j0 * HID + col]);
        *reinterpret_cast<float4*>(&Wsm[(g * CHUNKS_PER_G + i) * HID + j1]) =
            *reinterpret_cast<const float4*>(&Whh[j1 * HID + col]);
    }

    // ---- register W rows: Whh cols 64g+32 .. 64g+63 (16 u64 per j) ----
    u64 wr0[RF_U64], wr1[RF_U64];
    #pragma unroll
    for (int m = 0; m < RF_U64; ++m) {
        const int col = ROWS_PER_G * g + SMEM_ROWS_G + 2 * m;
        wr0[m] = *reinterpret_cast<const u64*>(&Whh[j0 * HID + col]);
        wr1[m] = *reinterpret_cast<const u64*>(&Whh[j1 * HID + col]);
    }

    // ---- finalize identity: one (batch, j) item per thread ----
    const int  fb   = jl >> 6;                 // 0 = batch A, 1 = batch B
    const int  fr   = jl & 63;                 // local row in slice
    const int  fj   = ROWS_PER_G * g + fr;     // global j
    const int  fbat = fb ? b1 : b0;

    float* myA = haug + (g * 2 + 0) * HAUG_STRIDE;
    float* myB = haug + (g * 2 + 1) * HAUG_STRIDE;
    float* fbuf = fb ? myB : myA;              // slice this thread finalizes into

    // ---- initial h staging (each thread stages its finalize item) ----
    fbuf[fr] = h0[fbat * HID + fj];
    __syncthreads();

    const ulonglong2* wp0 = Wsm + (size_t)(g * CHUNKS_PER_G) * HID + j0;
    const ulonglong2* wp1 = Wsm + (size_t)(g * CHUNKS_PER_G) * HID + j1;

    // ---- prime depth-1 W lookahead (chunk 0) ----
    ulonglong2 wb0 = wp0[0];
    ulonglong2 wb1 = wp1[0];

    for (int t = 0; t < T_STEPS; ++t) {
        float* redp = red + (t & 1) * RED_PAR_FLOATS;

        // prefetch this step's static pre-activation for my finalize item
        const float pre_v = g_pre[((size_t)t * BATCH + fbat) * HID + fj];

        // ---- interleaved FMA phase: (c r) x 8 slots ----
        u64 aA0 = 0, aA1 = 0, aB0 = 0, aB1 = 0;
        int ci = 0, ri = 0;

        #pragma unroll
        for (int k = 0; k < NSLOTS; ++k) {
            if (k & 1) {
                // RF slot ri: local rows 32+4*ri
                ulonglong2 ha = *reinterpret_cast<const ulonglong2*>(&myA[SMEM_ROWS_G + 4 * ri]);
                ulonglong2 hb = *reinterpret_cast<const ulonglong2*>(&myB[SMEM_ROWS_G + 4 * ri]);
                aA0 = fma2(wr0[2 * ri], ha.x, aA0);  aA0 = fma2(wr0[2 * ri + 1], ha.y, aA0);
                aA1 = fma2(wr1[2 * ri], ha.x, aA1);  aA1 = fma2(wr1[2 * ri + 1], ha.y, aA1);
                aB0 = fma2(wr0[2 * ri], hb.x, aB0);  aB0 = fma2(wr0[2 * ri + 1], hb.y, aB0);
                aB1 = fma2(wr1[2 * ri], hb.x, aB1);  aB1 = fma2(wr1[2 * ri + 1], hb.y, aB1);
                ++ri;
            } else {
                // chunk slot ci: consume buffered W, issue chunk (ci+1)%8;
                // last chunk slot fetches NEXT step's chunk 0 pre-barrier.
                const ulonglong2 w0 = wb0;
                const ulonglong2 w1 = wb1;
                int nc = ci + 1;
                if (nc >= CHUNKS_PER_G) nc = 0;
                wb0 = wp0[(size_t)nc * HID];
                wb1 = wp1[(size_t)nc * HID];

                ulonglong2 ha = *reinterpret_cast<const ulonglong2*>(&myA[4 * ci]);
                ulonglong2 hb = *reinterpret_cast<const ulonglong2*>(&myB[4 * ci]);
                aA0 = fma2(w0.x, ha.x, aA0);  aA0 = fma2(w0.y, ha.y, aA0);
                aA1 = fma2(w1.x, ha.x, aA1);  aA1 = fma2(w1.y, ha.y, aA1);
                aB0 = fma2(w0.x, hb.x, aB0);  aB0 = fma2(w0.y, hb.y, aB0);
                aB1 = fma2(w1.x, hb.x, aB1);  aB1 = fma2(w1.y, hb.y, aB1);
                ++ci;
            }
        }

        redp[(0 * NGROUP + g) * HID + j0] = sum2(aA0);
        redp[(0 * NGROUP + g) * HID + j1] = sum2(aA1);
        redp[(1 * NGROUP + g) * HID + j0] = sum2(aB0);
        redp[(1 * NGROUP + g) * HID + j1] = sum2(aB1);
        __syncthreads();                       // the ONE full-CTA barrier

        // ---- finalize my single (batch, j) item ----
        {
            const float* rb = redp + fb * NGROUP * HID;
            const float s = rb[0 * HID + fj] + rb[1 * HID + fj]
                          + rb[2 * HID + fj] + rb[3 * HID + fj];
            const float hn = fmaxf(fbuf[fr] * 0.8f + (s + pre_v) * 0.2f, 0.f);
            if (out) out[((size_t)t * BATCH + fbat) * HID + fj] = hn;
            fbuf[fr] = hn;
        }

        asm volatile("bar.sync %0, %1;" :: "r"(g + 1), "r"(128) : "memory");
    }

    if (hlast)
        hlast[fbat * HID + fj] = fbuf[fr];
}

extern "C" void kernel_launch(void* const* d_in, const int* in_sizes, int n_in,
                              void* d_out, int out_size)
{
    const float* x     = (const float*)d_in[0];   // [512,256,64]
    const float* h0    = (const float*)d_in[1];   // [256,256]
    const float* noise = (const float*)d_in[2];   // [512,256]
    const float* Win   = (const float*)d_in[3];   // [256,64]
    const float* bin   = (const float*)d_in[4];   // [256]
    const float* Whh   = (const float*)d_in[5];   // [256,256]
    const float* bhh   = (const float*)d_in[6];   // [256]

    const size_t TBH = (size_t)T_STEPS * BATCH * HID;
    const size_t BH  = (size_t)BATCH * HID;

    float* out   = nullptr;
    float* hlast = nullptr;
    if ((size_t)out_size >= TBH) {
        out = (float*)d_out;
        if ((size_t)out_size >= TBH + BH) hlast = (float*)d_out + TBH;
    } else {
        hlast = (float*)d_out;
    }

    static bool attr_set = false;
    if (!attr_set) {
        cudaFuncSetAttribute(ctrnn_rec_kernel,
                             cudaFuncAttributeMaxDynamicSharedMemorySize, SMEM_TOTAL);
        attr_set = true;
    }

    ctrnn_prepass<<<PP_CTAS, PP_THR>>>(x, noise, Win, bin, bhh);
    ctrnn_rec_kernel<<<NCTA, NTHR, SMEM_TOTAL>>>(h0, Whh, out, hlast);
}